// round 1
// baseline (speedup 1.0000x reference)
#include <cuda_runtime.h>

#define FULLMASK 0xffffffffu

__device__ __forceinline__ float silu_f(float x) {
    return x / (1.0f + __expf(-x));
}

// ---------------------------------------------------------------------------
// Edge kernel: one filter net over all edges.
//   ev_diff = ev[s] - ev[r]; ev_inv = segsum(ev_diff^2)
//   h = silu(silu(rbf(d) @ wr1 + br1) @ wr2 + br2)
//   e = silu(silu(ev_inv @ we1 + be1) @ we2 + be2)
//   out[e][:] = h + e
// One warp handles 4 edges at a time; lane owns 4 consecutive output columns.
// All weights live in shared memory; h1 staged in per-warp smem buffer.
// ---------------------------------------------------------------------------
__global__ __launch_bounds__(512, 1)
void edge_filter_kernel(const float* __restrict__ evf,
                        const int*   __restrict__ senders,
                        const int*   __restrict__ receivers,
                        const float* __restrict__ lengths,
                        const float* __restrict__ wr1, const float* __restrict__ br1,
                        const float* __restrict__ wr2, const float* __restrict__ br2,
                        const float* __restrict__ we1, const float* __restrict__ be1,
                        const float* __restrict__ we2, const float* __restrict__ be2,
                        float* __restrict__ outw, int E)
{
    extern __shared__ float sm[];
    float* wr1s  = sm;               // 32*128  = 4096
    float* wr2s  = wr1s + 4096;      // 128*128 = 16384
    float* we1s  = wr2s + 16384;     // 4*32    = 128
    float* we2s  = we1s + 128;       // 32*128  = 4096
    float* br1s  = we2s + 4096;      // 128
    float* br2s  = br1s + 128;       // 128
    float* be1s  = br2s + 128;       // 32
    float* be2s  = be1s + 32;        // 128
    float* h1buf = be2s + 128;       // 16 warps * 4 edges * 128 = 8192

    const int tid = threadIdx.x;
    for (int i = tid; i < 4096;  i += 512) wr1s[i] = wr1[i];
    for (int i = tid; i < 16384; i += 512) wr2s[i] = wr2[i];
    for (int i = tid; i < 4096;  i += 512) we2s[i] = we2[i];
    if (tid < 128) { we1s[tid] = we1[tid]; br1s[tid] = br1[tid];
                     br2s[tid] = br2[tid]; be2s[tid] = be2[tid]; }
    if (tid < 32)  be1s[tid] = be1[tid];
    __syncthreads();

    const int lane = tid & 31;
    const int warp = tid >> 5;
    float* h1w = h1buf + warp * 512;

    const int c0 = lane * 4;
    const float4 br1v = *(const float4*)&br1s[c0];
    const float4 br2v = *(const float4*)&br2s[c0];
    const float4 be2v = *(const float4*)&be2s[c0];
    const float  be1v = be1s[lane];
    float we1l[4];
    #pragma unroll
    for (int q = 0; q < 4; q++) we1l[q] = we1s[q * 32 + lane];

    const float center = (float)lane * (5.0f / 31.0f);
    const float GAMMA  = 0.5f * (31.0f / 5.0f) * (31.0f / 5.0f);

    const int nGroups = (E + 3) >> 2;
    const int gstride = gridDim.x * 16;

    for (int g = blockIdx.x * 16 + warp; g < nGroups; g += gstride) {
        const int ebase = g * 4;

        int   sI[4], rI[4];
        float dI[4];
        #pragma unroll
        for (int ei = 0; ei < 4; ei++) {
            int e  = ebase + ei;
            int ee = (e < E) ? e : 0;
            sI[ei] = senders[ee];
            rI[ei] = receivers[ee];
            dI[ei] = lengths[ee];
        }

        // ev_diff invariants (4 per edge), broadcast to all lanes via shfl
        float inv[4][4];
        #pragma unroll
        for (int ei = 0; ei < 4; ei++) {
            float p = 0.0f;
            if (lane < 16) {
                float a = evf[sI[ei] * 16 + lane] - evf[rI[ei] * 16 + lane];
                p = a * a;
            }
            inv[ei][0] = 0.f; inv[ei][1] = 0.f; inv[ei][2] = 0.f; inv[ei][3] = 0.f;
            const int SEG[16] = {0,1,1,1,2,2,2,2,2,3,3,3,3,3,3,3};
            #pragma unroll
            for (int k = 0; k < 16; k++) {
                float v = __shfl_sync(FULLMASK, p, k);
                inv[ei][SEG[k]] += v;
            }
        }

        // rbf: lane j holds rbf_j for each edge
        float rbf[4];
        #pragma unroll
        for (int ei = 0; ei < 4; ei++) {
            float t = dI[ei] - center;
            rbf[ei] = __expf(-GAMMA * t * t);
        }

        // e1 = silu(inv @ we1 + be1): lane holds column `lane`
        float e1r[4];
        #pragma unroll
        for (int ei = 0; ei < 4; ei++) {
            float a = be1v;
            #pragma unroll
            for (int q = 0; q < 4; q++) a = fmaf(inv[ei][q], we1l[q], a);
            e1r[ei] = silu_f(a);
        }

        // stage 1: h1 = silu(rbf @ wr1 + br1)
        float4 acc1[4];
        #pragma unroll
        for (int ei = 0; ei < 4; ei++) acc1[ei] = br1v;
        #pragma unroll 8
        for (int j = 0; j < 32; j++) {
            float4 w4 = *(const float4*)&wr1s[j * 128 + c0];
            #pragma unroll
            for (int ei = 0; ei < 4; ei++) {
                float rj = __shfl_sync(FULLMASK, rbf[ei], j);
                acc1[ei].x = fmaf(rj, w4.x, acc1[ei].x);
                acc1[ei].y = fmaf(rj, w4.y, acc1[ei].y);
                acc1[ei].z = fmaf(rj, w4.z, acc1[ei].z);
                acc1[ei].w = fmaf(rj, w4.w, acc1[ei].w);
            }
        }
        __syncwarp();
        #pragma unroll
        for (int ei = 0; ei < 4; ei++) {
            float4 h;
            h.x = silu_f(acc1[ei].x); h.y = silu_f(acc1[ei].y);
            h.z = silu_f(acc1[ei].z); h.w = silu_f(acc1[ei].w);
            *(float4*)&h1w[ei * 128 + c0] = h;
        }
        __syncwarp();

        // stage 2: h2 = silu(h1 @ wr2 + br2)
        float4 acc2[4];
        #pragma unroll
        for (int ei = 0; ei < 4; ei++) acc2[ei] = br2v;
        #pragma unroll 4
        for (int jg = 0; jg < 32; jg++) {
            float4 w0 = *(const float4*)&wr2s[(4 * jg + 0) * 128 + c0];
            float4 w1 = *(const float4*)&wr2s[(4 * jg + 1) * 128 + c0];
            float4 w2 = *(const float4*)&wr2s[(4 * jg + 2) * 128 + c0];
            float4 w3 = *(const float4*)&wr2s[(4 * jg + 3) * 128 + c0];
            #pragma unroll
            for (int ei = 0; ei < 4; ei++) {
                float4 h4 = *(const float4*)&h1w[ei * 128 + jg * 4];
                acc2[ei].x = fmaf(h4.x, w0.x, acc2[ei].x);
                acc2[ei].y = fmaf(h4.x, w0.y, acc2[ei].y);
                acc2[ei].z = fmaf(h4.x, w0.z, acc2[ei].z);
                acc2[ei].w = fmaf(h4.x, w0.w, acc2[ei].w);
                acc2[ei].x = fmaf(h4.y, w1.x, acc2[ei].x);
                acc2[ei].y = fmaf(h4.y, w1.y, acc2[ei].y);
                acc2[ei].z = fmaf(h4.y, w1.z, acc2[ei].z);
                acc2[ei].w = fmaf(h4.y, w1.w, acc2[ei].w);
                acc2[ei].x = fmaf(h4.z, w2.x, acc2[ei].x);
                acc2[ei].y = fmaf(h4.z, w2.y, acc2[ei].y);
                acc2[ei].z = fmaf(h4.z, w2.z, acc2[ei].z);
                acc2[ei].w = fmaf(h4.z, w2.w, acc2[ei].w);
                acc2[ei].x = fmaf(h4.w, w3.x, acc2[ei].x);
                acc2[ei].y = fmaf(h4.w, w3.y, acc2[ei].y);
                acc2[ei].z = fmaf(h4.w, w3.z, acc2[ei].z);
                acc2[ei].w = fmaf(h4.w, w3.w, acc2[ei].w);
            }
        }

        // stage e2: e2 = silu(e1 @ we2 + be2)
        float4 accE[4];
        #pragma unroll
        for (int ei = 0; ei < 4; ei++) accE[ei] = be2v;
        #pragma unroll 8
        for (int j = 0; j < 32; j++) {
            float4 w4 = *(const float4*)&we2s[j * 128 + c0];
            #pragma unroll
            for (int ei = 0; ei < 4; ei++) {
                float ej = __shfl_sync(FULLMASK, e1r[ei], j);
                accE[ei].x = fmaf(ej, w4.x, accE[ei].x);
                accE[ei].y = fmaf(ej, w4.y, accE[ei].y);
                accE[ei].z = fmaf(ej, w4.z, accE[ei].z);
                accE[ei].w = fmaf(ej, w4.w, accE[ei].w);
            }
        }

        // out = silu(acc2) + silu(accE)
        #pragma unroll
        for (int ei = 0; ei < 4; ei++) {
            int e = ebase + ei;
            if (e < E) {
                float4 o;
                o.x = silu_f(acc2[ei].x) + silu_f(accE[ei].x);
                o.y = silu_f(acc2[ei].y) + silu_f(accE[ei].y);
                o.z = silu_f(acc2[ei].z) + silu_f(accE[ei].z);
                o.w = silu_f(acc2[ei].w) + silu_f(accE[ei].w);
                *(float4*)&outw[(size_t)e * 128 + c0] = o;
            }
        }
        __syncwarp();
    }
}

// ---------------------------------------------------------------------------
// Node kernel:
//   att_inv = 2*inv, att_ev = 2*ev, ev_invs = segsum(att_ev^2)
//   t = [att_inv, ev_invs] @ w_int + b_int     (132 x 132)
//   out_inv = att_inv + t[:,:128]
//   out_ev  = att_ev * (1 + t[:,128+SEG])
// Block (33, 8): 33 column-groups of 4 cols, 8 node-groups of 4 nodes.
// w_int cached in smem; 4x4 register tile per thread.
// ---------------------------------------------------------------------------
__global__ __launch_bounds__(264, 2)
void node_kernel(const float* __restrict__ inv_f, const float* __restrict__ ev_f,
                 const float* __restrict__ w_int, const float* __restrict__ b_int,
                 float* __restrict__ out_inv, float* __restrict__ out_ev, int N)
{
    extern __shared__ float sm[];
    float* Wsh = sm;                 // 132*132 = 17424
    float* bsh = Wsh + 17424;        // 132
    float* xs  = bsh + 132;          // 32*132 = 4224
    float* aev = xs + 4224;          // 32*16  = 512

    const int tx  = threadIdx.x;     // 0..32
    const int ty  = threadIdx.y;     // 0..7
    const int tid = tx + 33 * ty;
    const int NT  = 264;

    for (int i = tid; i < 17424; i += NT) Wsh[i] = w_int[i];
    if (tid < 132) bsh[tid] = b_int[tid];
    __syncthreads();

    const int nTiles = (N + 31) / 32;
    for (int tile = blockIdx.x; tile < nTiles; tile += gridDim.x) {
        const int base = tile * 32;

        for (int i = tid; i < 32 * 132; i += NT) {
            int l = i / 132, c = i % 132;
            int n = base + l;
            float v = 0.0f;
            if (n < N) {
                if (c < 128) {
                    v = 2.0f * inv_f[(size_t)n * 128 + c];
                } else {
                    const int st[5] = {0, 1, 4, 9, 16};
                    int s = c - 128;
                    float acc = 0.0f;
                    for (int k = st[s]; k < st[s + 1]; k++) {
                        float a = 2.0f * ev_f[(size_t)n * 16 + k];
                        acc = fmaf(a, a, acc);
                    }
                    v = acc;
                }
            }
            xs[l * 132 + c] = v;
        }
        for (int i = tid; i < 512; i += NT) {
            int l = i / 16, k = i % 16;
            int n = base + l;
            aev[i] = (n < N) ? 2.0f * ev_f[(size_t)n * 16 + k] : 0.0f;
        }
        __syncthreads();

        const int c0 = tx * 4;
        float acc[4][4];
        #pragma unroll
        for (int i = 0; i < 4; i++)
            #pragma unroll
            for (int k = 0; k < 4; k++) acc[i][k] = 0.0f;

        #pragma unroll 4
        for (int j = 0; j < 132; j++) {
            float4 w4 = *(const float4*)&Wsh[j * 132 + c0];
            #pragma unroll
            for (int i = 0; i < 4; i++) {
                float xv = xs[(ty * 4 + i) * 132 + j];
                acc[i][0] = fmaf(xv, w4.x, acc[i][0]);
                acc[i][1] = fmaf(xv, w4.y, acc[i][1]);
                acc[i][2] = fmaf(xv, w4.z, acc[i][2]);
                acc[i][3] = fmaf(xv, w4.w, acc[i][3]);
            }
        }

        const float4 bv = *(const float4*)&bsh[c0];
        #pragma unroll
        for (int i = 0; i < 4; i++) {
            int n = base + ty * 4 + i;
            if (n >= N) continue;
            float t0 = acc[i][0] + bv.x;
            float t1 = acc[i][1] + bv.y;
            float t2 = acc[i][2] + bv.z;
            float t3 = acc[i][3] + bv.w;
            if (tx < 32) {
                float4 o;
                o.x = xs[(ty * 4 + i) * 132 + c0 + 0] + t0;
                o.y = xs[(ty * 4 + i) * 132 + c0 + 1] + t1;
                o.z = xs[(ty * 4 + i) * 132 + c0 + 2] + t2;
                o.w = xs[(ty * 4 + i) * 132 + c0 + 3] + t3;
                *(float4*)&out_inv[(size_t)n * 128 + c0] = o;
            } else {
                float tb[4] = {t0, t1, t2, t3};
                const int SEG[16] = {0,1,1,1,2,2,2,2,2,3,3,3,3,3,3,3};
                #pragma unroll
                for (int k = 0; k < 16; k++) {
                    out_ev[(size_t)n * 16 + k] =
                        aev[(ty * 4 + i) * 16 + k] * (1.0f + tb[SEG[k]]);
                }
            }
        }
        __syncthreads();
    }
}

// ---------------------------------------------------------------------------
// Launch
// ---------------------------------------------------------------------------
static const int EDGE_SMEM = 33312 * 4;   // 133248 B
static const int NODE_SMEM = 22292 * 4;   // 89168 B

extern "C" void kernel_launch(void* const* d_in, const int* in_sizes, int n_in,
                              void* d_out, int out_size)
{
    const float* inv_f     = (const float*)d_in[0];
    const float* ev_f      = (const float*)d_in[1];
    const int*   senders   = (const int*)  d_in[2];
    const int*   receivers = (const int*)  d_in[3];
    // d_in[4] sh_vectors: unused by reference
    const float* lengths   = (const float*)d_in[5];
    // d_in[6] cutoffs: unused by reference

    const float* fi_rbf_w1 = (const float*)d_in[7];
    const float* fi_rbf_b1 = (const float*)d_in[8];
    const float* fi_rbf_w2 = (const float*)d_in[9];
    const float* fi_rbf_b2 = (const float*)d_in[10];
    const float* fi_ev_w1  = (const float*)d_in[11];
    const float* fi_ev_b1  = (const float*)d_in[12];
    const float* fi_ev_w2  = (const float*)d_in[13];
    const float* fi_ev_b2  = (const float*)d_in[14];
    const float* fe_rbf_w1 = (const float*)d_in[15];
    const float* fe_rbf_b1 = (const float*)d_in[16];
    const float* fe_rbf_w2 = (const float*)d_in[17];
    const float* fe_rbf_b2 = (const float*)d_in[18];
    const float* fe_ev_w1  = (const float*)d_in[19];
    const float* fe_ev_b1  = (const float*)d_in[20];
    const float* fe_ev_w2  = (const float*)d_in[21];
    const float* fe_ev_b2  = (const float*)d_in[22];
    const float* w_int     = (const float*)d_in[23];
    const float* b_int     = (const float*)d_in[24];

    const int N = in_sizes[0] / 128;
    const int E = in_sizes[2];

    float* out     = (float*)d_out;
    float* out_inv = out;
    float* out_ev  = out + (size_t)N * 128;
    float* fw_inv  = out + (size_t)N * 144;
    float* fw_ev   = fw_inv + (size_t)E * 128;

    cudaFuncSetAttribute(node_kernel,
                         cudaFuncAttributeMaxDynamicSharedMemorySize, NODE_SMEM);
    cudaFuncSetAttribute(edge_filter_kernel,
                         cudaFuncAttributeMaxDynamicSharedMemorySize, EDGE_SMEM);

    node_kernel<<<304, dim3(33, 8), NODE_SMEM>>>(
        inv_f, ev_f, w_int, b_int, out_inv, out_ev, N);

    edge_filter_kernel<<<152, 512, EDGE_SMEM>>>(
        ev_f, senders, receivers, lengths,
        fi_rbf_w1, fi_rbf_b1, fi_rbf_w2, fi_rbf_b2,
        fi_ev_w1,  fi_ev_b1,  fi_ev_w2,  fi_ev_b2,
        fw_inv, E);

    edge_filter_kernel<<<152, 512, EDGE_SMEM>>>(
        ev_f, senders, receivers, lengths,
        fe_rbf_w1, fe_rbf_b1, fe_rbf_w2, fe_rbf_b2,
        fe_ev_w1,  fe_ev_b1,  fe_ev_w2,  fe_ev_b2,
        fw_ev, E);
}